// round 6
// baseline (speedup 1.0000x reference)
#include <cuda_runtime.h>
#include <cuda_bf16.h>
#include <cstdint>
#include <cstddef>

// VectorQuantizer on GB300 (sm_103a)
// 1-term bf16 HMMA scoring + exact fp32 rescore of tight-margin pixels.
// z_e: (16,256,64,64) fp32 ; embedding: (1024,256) fp32

#define NEMB 1024
#define EDIM 256
#define HW   4096
#define NPIX 65536
#define NC   16777216

#define MARGIN  0.75f
#define FLAGCAP 65536

#define PITCH   528              // 512B payload + 16B pad (conflict-free ldmatrix)
#define TILEB   67584            // 128 rows * PITCH
#define SM_E2   (3 * TILEB)      // e2 after A + 2 B buffers
#define SM_MRG  (3 * TILEB + 4096)
#define SM_TOT  (3 * TILEB + 4096 + 2048)

// ---- device scratch ----
__device__ __align__(128) __nv_bfloat16 g_A0[(size_t)NPIX * EDIM];  // [pix][k] bf16
__device__ __align__(128) __nv_bfloat16 g_B0[NEMB * EDIM];          // [code][k] bf16
__device__ __align__(16) float  g_e2[NEMB];
__device__ int    g_idx[NPIX];
__device__ double g_part[2048];
__device__ int    g_nflag;
__device__ int    g_flag[FLAGCAP];

// ---- helpers ----
static __device__ __forceinline__ uint32_t s2u(const void* p) {
    uint32_t a;
    asm("{ .reg .u64 t; cvta.to.shared.u64 t, %1; cvt.u32.u64 %0, t; }" : "=r"(a) : "l"(p));
    return a;
}
static __device__ __forceinline__ void cpa16(uint32_t dst, const void* src) {
    asm volatile("cp.async.cg.shared.global [%0], [%1], 16;" :: "r"(dst), "l"(src));
}

#define LDSM_X4(r0, r1, r2, r3, a) \
    asm volatile("ldmatrix.sync.aligned.m8n8.x4.shared.b16 {%0,%1,%2,%3}, [%4];" \
                 : "=r"(r0), "=r"(r1), "=r"(r2), "=r"(r3) : "r"(a))
#define MMA16816(d, a0, a1, a2, a3, b0, b1) \
    asm volatile("mma.sync.aligned.m16n8k16.row.col.f32.bf16.bf16.f32 " \
                 "{%0,%1,%2,%3}, {%4,%5,%6,%7}, {%8,%9}, {%0,%1,%2,%3};" \
                 : "+f"((d)[0]), "+f"((d)[1]), "+f"((d)[2]), "+f"((d)[3]) \
                 : "r"(a0), "r"(a1), "r"(a2), "r"(a3), "r"(b0), "r"(b1))

// ============================================================
// K1: z_e -> bf16 plane, transposed to [pix][k].
// ============================================================
__global__ __launch_bounds__(256) void k_split(const float* __restrict__ z) {
    __shared__ float sz[32][257];
    const int t = threadIdx.x;
    const int pix0 = blockIdx.x << 5;
    const float* zb = z + (((size_t)(pix0 >> 12)) << 20) + (pix0 & 4095);

    if (blockIdx.x == 0 && t == 0) g_nflag = 0;

    #pragma unroll 8
    for (int it = 0; it < 32; ++it) {
        int slot = t + (it << 8);
        int k = slot >> 5, p = slot & 31;
        sz[p][k] = zb[(size_t)k * HW + p];
    }
    __syncthreads();

    #pragma unroll
    for (int it = 0; it < 4; ++it) {
        int g = t + (it << 8);
        int p = g >> 5, k0 = (g & 31) << 3;
        union { __nv_bfloat16 h[8]; uint4 v; } u0;
        #pragma unroll
        for (int j = 0; j < 8; ++j) u0.h[j] = __float2bfloat16(sz[p][k0 + j]);
        *reinterpret_cast<uint4*>(&g_A0[((size_t)(pix0 + p) << 8) + k0]) = u0.v;
    }
}

// ============================================================
// K2: embedding -> bf16 + exact fp32 norms.
// ============================================================
__global__ __launch_bounds__(256) void k_prep_e(const float* __restrict__ emb) {
    int warp = (blockIdx.x * blockDim.x + threadIdx.x) >> 5;
    int lane = threadIdx.x & 31;
    if (warp >= NEMB) return;
    const float* row = emb + (size_t)warp * EDIM;
    int k0 = lane << 3;
    float4 v0 = *reinterpret_cast<const float4*>(row + k0);
    float4 v1 = *reinterpret_cast<const float4*>(row + k0 + 4);
    float xs[8] = {v0.x, v0.y, v0.z, v0.w, v1.x, v1.y, v1.z, v1.w};
    union { __nv_bfloat16 h[8]; uint4 v; } u0;
    float s = 0.f;
    #pragma unroll
    for (int j = 0; j < 8; ++j) {
        s += xs[j] * xs[j];
        u0.h[j] = __float2bfloat16(xs[j]);
    }
    *reinterpret_cast<uint4*>(&g_B0[((size_t)warp << 8) + k0]) = u0.v;
    #pragma unroll
    for (int o = 16; o; o >>= 1) s += __shfl_xor_sync(0xFFFFFFFFu, s, o);
    if (lane == 0) g_e2[warp] = s;
}

// ============================================================
// K3: HMMA scoring + fused argmin.
// CTA: 128 pixels x 1024 codes. A staged once (66KB), B streamed in
// 128-code full-K chunks (66KB each, double-buffered). Warp tile 32x64.
// Final cross-warp merge over the two warp_n halves per pixel.
// ============================================================
__global__ __launch_bounds__(256, 1) void k_mma() {
    extern __shared__ char smem[];
    const uint32_t sA = s2u(smem);
    const uint32_t sB = sA + TILEB;
    float* se2 = reinterpret_cast<float*>(smem + SM_E2);

    const int t = threadIdx.x;
    const int wid = t >> 5;
    const int lane = t & 31;
    const int warp_m = wid & 3;       // 4 m-positions x 32 pixels
    const int warp_n = wid >> 2;      // 2 n-positions x 64 codes
    const int pix0 = blockIdx.x << 7;

    #pragma unroll
    for (int i = 0; i < 4; ++i) se2[t + (i << 8)] = g_e2[t + (i << 8)];

    // ---- stage A (128x256 bf16) + B chunk 0 via cp.async ----
    #pragma unroll
    for (int i = 0; i < 16; ++i) {
        int idx = t + (i << 8);
        int r = idx >> 5, c = idx & 31;
        cpa16(sA + r * PITCH + (c << 4), &g_A0[((size_t)(pix0 + r) << 8) + (c << 3)]);
    }
    #pragma unroll
    for (int i = 0; i < 16; ++i) {
        int idx = t + (i << 8);
        int r = idx >> 5, c = idx & 31;
        cpa16(sB + r * PITCH + (c << 4), &g_B0[((size_t)r << 8) + (c << 3)]);
    }
    asm volatile("cp.async.commit_group;" ::: "memory");

    // ---- ldmatrix lane addresses ----
    const uint32_t aoff = (uint32_t)((warp_m * 32 + (lane & 15)) * PITCH + ((lane >> 4) << 4));
    const int br = (lane & 7) + ((lane >> 4) << 3);
    const uint32_t boff = (uint32_t)((warp_n * 64 + br) * PITCH + (((lane >> 3) & 1) << 4));

    float bv[4], b2[4];
    int   bi[4];
    #pragma unroll
    for (int s = 0; s < 4; ++s) { bv[s] = 3.402823466e38f; b2[s] = 3.402823466e38f; bi[s] = 0; }

    #pragma unroll 1
    for (int c = 0; c < 8; ++c) {
        // prefetch next chunk into the other buffer
        if (c < 7) {
            const uint32_t bb = sB + ((c + 1) & 1) * TILEB;
            #pragma unroll
            for (int i = 0; i < 16; ++i) {
                int idx = t + (i << 8);
                int r = idx >> 5, cc = idx & 31;
                cpa16(bb + r * PITCH + (cc << 4),
                      &g_B0[((((size_t)(c + 1) << 7) + r) << 8) + (cc << 3)]);
            }
            asm volatile("cp.async.commit_group;" ::: "memory");
            asm volatile("cp.async.wait_group 1;" ::: "memory");
        } else {
            asm volatile("cp.async.wait_group 0;" ::: "memory");
        }
        __syncthreads();

        float acc[2][8][4];
        #pragma unroll
        for (int mi = 0; mi < 2; ++mi)
            #pragma unroll
            for (int ni = 0; ni < 8; ++ni)
                #pragma unroll
                for (int j = 0; j < 4; ++j) acc[mi][ni][j] = 0.f;

        const uint32_t bufb = sB + (c & 1) * TILEB + boff;
        const uint32_t abase = sA + aoff;

        #pragma unroll 4
        for (int ks = 0; ks < 16; ++ks) {
            uint32_t a0[4], a1[4];
            LDSM_X4(a0[0], a0[1], a0[2], a0[3], abase + ks * 32);
            LDSM_X4(a1[0], a1[1], a1[2], a1[3], abase + 16 * PITCH + ks * 32);
            uint32_t b[4][4];
            #pragma unroll
            for (int gi = 0; gi < 4; ++gi)
                LDSM_X4(b[gi][0], b[gi][1], b[gi][2], b[gi][3],
                        bufb + gi * (16 * PITCH) + ks * 32);
            #pragma unroll
            for (int ni = 0; ni < 8; ++ni) {
                const int gi = ni >> 1, hh = (ni & 1) << 1;
                MMA16816(acc[0][ni], a0[0], a0[1], a0[2], a0[3], b[gi][hh], b[gi][hh + 1]);
                MMA16816(acc[1][ni], a1[0], a1[1], a1[2], a1[3], b[gi][hh], b[gi][hh + 1]);
            }
        }

        // ---- epilogue: scores + running (best, 2nd, idx) ----
        const int cb = (c << 7) + warp_n * 64 + ((lane & 3) << 1);
        #pragma unroll
        for (int ni = 0; ni < 8; ++ni) {
            const int code = cb + ni * 8;
            float2 e2v = *reinterpret_cast<const float2*>(&se2[code]);
            #pragma unroll
            for (int mi = 0; mi < 2; ++mi) {
                #pragma unroll
                for (int half = 0; half < 2; ++half) {
                    const int s = mi * 2 + half;
                    float s0 = fmaf(-2.f, acc[mi][ni][half * 2],     e2v.x);
                    float s1 = fmaf(-2.f, acc[mi][ni][half * 2 + 1], e2v.y);
                    if (s0 < bv[s]) { b2[s] = bv[s]; bv[s] = s0; bi[s] = code; }
                    else if (s0 < b2[s]) b2[s] = s0;
                    if (s1 < bv[s]) { b2[s] = bv[s]; bv[s] = s1; bi[s] = code + 1; }
                    else if (s1 < b2[s]) b2[s] = s1;
                }
            }
        }
        __syncthreads();
    }

    // ---- merge across the 4 lanes sharing each pixel row ----
    #pragma unroll
    for (int o = 1; o <= 2; o <<= 1) {
        #pragma unroll
        for (int s = 0; s < 4; ++s) {
            float ov = __shfl_xor_sync(0xFFFFFFFFu, bv[s], o);
            float o2 = __shfl_xor_sync(0xFFFFFFFFu, b2[s], o);
            int   oi = __shfl_xor_sync(0xFFFFFFFFu, bi[s], o);
            if (ov < bv[s] || (ov == bv[s] && oi < bi[s])) {
                b2[s] = fminf(bv[s], o2);
                bv[s] = ov; bi[s] = oi;
            } else {
                b2[s] = fminf(b2[s], ov);
            }
        }
    }

    // ---- cross-warp merge: warp_n==1 stashes, warp_n==0 combines & writes ----
    float* mf  = reinterpret_cast<float*>(smem + SM_MRG);         // [128]
    float* m2  = mf + 128;                                        // [128]
    int*   mi_ = reinterpret_cast<int*>(m2 + 128);                // [128]
    if (warp_n == 1 && (lane & 3) == 0) {
        #pragma unroll
        for (int s = 0; s < 4; ++s) {
            int p = warp_m * 32 + ((s >> 1) << 4) + ((s & 1) << 3) + (lane >> 2);
            mf[p] = bv[s]; m2[p] = b2[s]; mi_[p] = bi[s];
        }
    }
    __syncthreads();
    if (warp_n == 0 && (lane & 3) == 0) {
        #pragma unroll
        for (int s = 0; s < 4; ++s) {
            int p = warp_m * 32 + ((s >> 1) << 4) + ((s & 1) << 3) + (lane >> 2);
            float ov = mf[p], o2v = m2[p];
            int   oi = mi_[p];
            float nb, nb2; int ni;
            if (ov < bv[s] || (ov == bv[s] && oi < bi[s])) {
                nb = ov;    ni = oi;    nb2 = fminf(bv[s], o2v);
            } else {
                nb = bv[s]; ni = bi[s]; nb2 = fminf(ov, b2[s]);
            }
            g_idx[pix0 + p] = ni;
            if (nb2 - nb < MARGIN) {
                int pos = atomicAdd(&g_nflag, 1);
                if (pos < FLAGCAP) g_flag[pos] = pix0 + p;
            }
        }
    }
}

// ============================================================
// K4: exact fp32 rescore of margin-flagged pixels (one warp each)
// ============================================================
__global__ __launch_bounds__(256) void k_fix(const float* __restrict__ z,
                                             const float* __restrict__ emb) {
    __shared__ float sx[8][256];
    const int w = threadIdx.x >> 5, lane = threadIdx.x & 31;
    int n = g_nflag; if (n > FLAGCAP) n = FLAGCAP;
    for (int f = blockIdx.x * 8 + w; f < n; f += gridDim.x * 8) {
        int pix = g_flag[f];
        const float* zb = z + (((size_t)(pix >> 12)) << 20) + (pix & 4095);
        for (int k = lane; k < EDIM; k += 32) sx[w][k] = zb[(size_t)k * HW];
        __syncwarp();
        float bv = 3.402823466e38f; int bi = 0;
        for (int c = lane; c < NEMB; c += 32) {
            const float* e = emb + (size_t)c * EDIM;
            float a0 = 0.f, a1 = 0.f, a2 = 0.f, a3 = 0.f;
            #pragma unroll 8
            for (int k = 0; k < EDIM; k += 4) {
                a0 = fmaf(sx[w][k],     e[k],     a0);
                a1 = fmaf(sx[w][k + 1], e[k + 1], a1);
                a2 = fmaf(sx[w][k + 2], e[k + 2], a2);
                a3 = fmaf(sx[w][k + 3], e[k + 3], a3);
            }
            float sc = g_e2[c] - 2.f * ((a0 + a1) + (a2 + a3));
            if (sc < bv) { bv = sc; bi = c; }
        }
        #pragma unroll
        for (int o = 16; o; o >>= 1) {
            float ov = __shfl_xor_sync(0xFFFFFFFFu, bv, o);
            int   oi = __shfl_xor_sync(0xFFFFFFFFu, bi, o);
            if (ov < bv || (ov == bv && oi < bi)) { bv = ov; bi = oi; }
        }
        if (lane == 0) g_idx[pix] = bi;
        __syncwarp();
    }
}

// ============================================================
// K5: gather z_q, write z_q_st = z_e + (z_q - z_e), loss partials
// ============================================================
__global__ __launch_bounds__(256)
void k_gather(const float* __restrict__ z, const float* __restrict__ emb,
              float* __restrict__ out) {
    __shared__ float sE[32 * 260];
    __shared__ float swarp[8];
    const int t = threadIdx.x;
    const int pix0 = blockIdx.x << 5;

    #pragma unroll
    for (int it = 0; it < 8; ++it) {
        int slot = t + (it << 8);
        int p = slot >> 6, c4 = slot & 63;
        int idx = g_idx[pix0 + p];
        float4 v = *reinterpret_cast<const float4*>(emb + (size_t)idx * EDIM + (c4 << 2));
        *reinterpret_cast<float4*>(&sE[p * 260 + (c4 << 2)]) = v;
    }
    __syncthreads();

    const float* zb = z   + (((size_t)(pix0 >> 12)) << 20) + (pix0 & 4095);
    float*       ob = out + (((size_t)(pix0 >> 12)) << 20) + (pix0 & 4095);

    float lsum = 0.f;
    #pragma unroll
    for (int it = 0; it < 8; ++it) {
        int slot = t + (it << 8);
        int hw = slot & 31, c4 = slot >> 5;
        float4 e = *reinterpret_cast<const float4*>(&sE[hw * 260 + (c4 << 2)]);
        float ev[4] = {e.x, e.y, e.z, e.w};
        #pragma unroll
        for (int j = 0; j < 4; ++j) {
            size_t gg = (size_t)((c4 << 2) + j) * HW + hw;
            float ze = zb[gg];
            float d = ev[j] - ze;
            ob[gg] = ze + d;
            lsum += d * d;
        }
    }
    #pragma unroll
    for (int o = 16; o; o >>= 1) lsum += __shfl_xor_sync(0xFFFFFFFFu, lsum, o);
    if ((t & 31) == 0) swarp[t >> 5] = lsum;
    __syncthreads();
    if (t == 0) {
        double s = 0.0;
        #pragma unroll
        for (int w = 0; w < 8; ++w) s += (double)swarp[w];
        g_part[blockIdx.x] = s;
    }
}

// ============================================================
// K6: loss finalize
// ============================================================
__global__ void k_loss(float* __restrict__ out, int out_size) {
    __shared__ double sd[256];
    int t = threadIdx.x;
    double s = 0.0;
    for (int i = t; i < 2048; i += 256) s += g_part[i];
    sd[t] = s;
    __syncthreads();
    for (int o = 128; o; o >>= 1) {
        if (t < o) sd[t] += sd[t + o];
        __syncthreads();
    }
    if (t == 0 && out_size > NC)
        out[NC] = (float)(0.25 * sd[0] / (double)NC);
}

// ============================================================
extern "C" void kernel_launch(void* const* d_in, const int* in_sizes, int n_in,
                              void* d_out, int out_size) {
    const float* z   = (const float*)d_in[0];
    const float* emb = (const float*)d_in[1];
    float* out = (float*)d_out;

    static bool attr_set = false;
    if (!attr_set) {
        cudaFuncSetAttribute(k_mma, cudaFuncAttributeMaxDynamicSharedMemorySize, SM_TOT);
        attr_set = true;
    }

    k_split <<<2048, 256>>>(z);
    k_prep_e<<<128,  256>>>(emb);
    k_mma   <<<512,  256, SM_TOT>>>();
    k_fix   <<<256,  256>>>(z, emb);
    k_gather<<<2048, 256>>>(z, emb, out);
    k_loss  <<<1,    256>>>(out, out_size);
}

// round 7
// speedup vs baseline: 1.5870x; 1.5870x over previous
#include <cuda_runtime.h>
#include <cuda_bf16.h>
#include <cstdint>
#include <cstddef>

// VectorQuantizer on GB300 (sm_103a)
// 1-term bf16 mma.sync scoring (R4-proven loop structure) + exact fp32 rescue.
// z_e: (16,256,64,64) fp32 ; embedding: (1024,256) fp32

#define NEMB 1024
#define EDIM 256
#define HW   4096
#define NPIX 65536
#define NC   16777216

#define MARGIN  0.5f
#define FLAGCAP 65536

#define PITCH 48                 // 32B payload + 16B pad; r*48 mod 128 covers all 8 banks
#define BUFB  6144               // 128 rows * 48

// ---- device scratch ----
__device__ __align__(128) __nv_bfloat16 g_A0[(size_t)NPIX * EDIM];  // [pix][k] bf16
__device__ __align__(128) __nv_bfloat16 g_B0[NEMB * EDIM];          // [code][k] bf16
__device__ __align__(16) float  g_e2[NEMB];
__device__ int    g_idx[NPIX];
__device__ double g_part[2048];
__device__ int    g_nflag;
__device__ int    g_flag[FLAGCAP];

// ---- helpers ----
static __device__ __forceinline__ uint32_t s2u(const void* p) {
    uint32_t a;
    asm("{ .reg .u64 t; cvta.to.shared.u64 t, %1; cvt.u32.u64 %0, t; }" : "=r"(a) : "l"(p));
    return a;
}
static __device__ __forceinline__ void cpa16(uint32_t dst, const void* src) {
    asm volatile("cp.async.cg.shared.global [%0], [%1], 16;" :: "r"(dst), "l"(src));
}

#define LDSM_X4(r0, r1, r2, r3, a) \
    asm volatile("ldmatrix.sync.aligned.m8n8.x4.shared.b16 {%0,%1,%2,%3}, [%4];" \
                 : "=r"(r0), "=r"(r1), "=r"(r2), "=r"(r3) : "r"(a))
#define MMA16816(d, a0, a1, a2, a3, b0, b1) \
    asm volatile("mma.sync.aligned.m16n8k16.row.col.f32.bf16.bf16.f32 " \
                 "{%0,%1,%2,%3}, {%4,%5,%6,%7}, {%8,%9}, {%0,%1,%2,%3};" \
                 : "+f"((d)[0]), "+f"((d)[1]), "+f"((d)[2]), "+f"((d)[3]) \
                 : "r"(a0), "r"(a1), "r"(a2), "r"(a3), "r"(b0), "r"(b1))

// ============================================================
// K1: z_e -> bf16 plane, transposed to [pix][k].
// ============================================================
__global__ __launch_bounds__(256) void k_split(const float* __restrict__ z) {
    __shared__ float sz[32][257];
    const int t = threadIdx.x;
    const int pix0 = blockIdx.x << 5;
    const float* zb = z + (((size_t)(pix0 >> 12)) << 20) + (pix0 & 4095);

    if (blockIdx.x == 0 && t == 0) g_nflag = 0;

    #pragma unroll 8
    for (int it = 0; it < 32; ++it) {
        int slot = t + (it << 8);
        int k = slot >> 5, p = slot & 31;
        sz[p][k] = zb[(size_t)k * HW + p];
    }
    __syncthreads();

    #pragma unroll
    for (int it = 0; it < 4; ++it) {
        int g = t + (it << 8);
        int p = g >> 5, k0 = (g & 31) << 3;
        union { __nv_bfloat16 h[8]; uint4 v; } u0;
        #pragma unroll
        for (int j = 0; j < 8; ++j) u0.h[j] = __float2bfloat16(sz[p][k0 + j]);
        *reinterpret_cast<uint4*>(&g_A0[((size_t)(pix0 + p) << 8) + k0]) = u0.v;
    }
}

// ============================================================
// K2: embedding -> bf16 + exact fp32 norms.
// ============================================================
__global__ __launch_bounds__(256) void k_prep_e(const float* __restrict__ emb) {
    int warp = (blockIdx.x * blockDim.x + threadIdx.x) >> 5;
    int lane = threadIdx.x & 31;
    if (warp >= NEMB) return;
    const float* row = emb + (size_t)warp * EDIM;
    int k0 = lane << 3;
    float4 v0 = *reinterpret_cast<const float4*>(row + k0);
    float4 v1 = *reinterpret_cast<const float4*>(row + k0 + 4);
    float xs[8] = {v0.x, v0.y, v0.z, v0.w, v1.x, v1.y, v1.z, v1.w};
    union { __nv_bfloat16 h[8]; uint4 v; } u0;
    float s = 0.f;
    #pragma unroll
    for (int j = 0; j < 8; ++j) {
        s += xs[j] * xs[j];
        u0.h[j] = __float2bfloat16(xs[j]);
    }
    *reinterpret_cast<uint4*>(&g_B0[((size_t)warp << 8) + k0]) = u0.v;
    #pragma unroll
    for (int o = 16; o; o >>= 1) s += __shfl_xor_sync(0xFFFFFFFFu, s, o);
    if (lane == 0) g_e2[warp] = s;
}

// ============================================================
// K3: mma.sync scoring + fused argmin (R4 structure, single term).
// CTA = 128 pixels x 1024 codes; warp owns 16 pixels x all 128 codes
// of the current chunk. 128 g-steps = 8 code-chunks x 16 k-steps.
// Per step: A chunk (128x16) + B chunk (128x16) double-buffered cp.async.
// ============================================================
__global__ __launch_bounds__(256, 2) void k_mma() {
    __shared__ __align__(16) char sA[2][BUFB];
    __shared__ __align__(16) char sB[2][BUFB];
    __shared__ float se2[NEMB];

    const int t = threadIdx.x;
    const int wid = t >> 5;
    const int lane = t & 31;
    const int pix0 = blockIdx.x << 7;

    #pragma unroll
    for (int i = 0; i < 4; ++i) se2[t + (i << 8)] = g_e2[t + (i << 8)];

    const uint32_t sAu = s2u(sA);
    const uint32_t sBu = s2u(sB);

    // cp.async roles: threads 0-127 -> A rows, 128-255 -> B rows
    const bool isB = t >= 128;
    const int  row = t & 127;
    const __nv_bfloat16* P0 = isB ? g_B0 : g_A0;
    const size_t rbase = isB ? ((size_t)row << 8) : ((size_t)(pix0 + row) << 8);
    const uint32_t dbase = (isB ? sBu : sAu) + row * PITCH;

    // ldmatrix lane addresses
    const uint32_t aoff = (uint32_t)((wid * 16 + (lane & 15)) * PITCH + ((lane >> 4) << 4));
    const uint32_t boff = (uint32_t)(((lane & 7) + ((lane >> 4) << 3)) * PITCH +
                                     (((lane >> 3) & 1) << 4));

    float bv[2] = {3.402823466e38f, 3.402823466e38f};
    float b2[2] = {3.402823466e38f, 3.402823466e38f};
    int   bi[2] = {0, 0};

    float acc[16][4];

    // prime: g-step 0 (cc=0, kc=0) into buffer 0
    cpa16(dbase + 0,  &P0[rbase + 0]);
    cpa16(dbase + 16, &P0[rbase + 8]);
    asm volatile("cp.async.commit_group;" ::: "memory");

    #pragma unroll 1
    for (int g = 0; g < 128; ++g) {
        const int buf = g & 1;
        if (g < 127) {
            const int gn = g + 1;
            const int cc = gn >> 4, kc = gn & 15;
            const size_t off = rbase + (isB ? ((size_t)cc << 15) : 0) + (kc << 4);
            const uint32_t d = dbase + ((gn & 1) ? BUFB : 0u);
            cpa16(d + 0,  &P0[off]);
            cpa16(d + 16, &P0[off + 8]);
            asm volatile("cp.async.commit_group;" ::: "memory");
            asm volatile("cp.async.wait_group 1;" ::: "memory");
        } else {
            asm volatile("cp.async.wait_group 0;" ::: "memory");
        }
        __syncthreads();

        if ((g & 15) == 0) {
            #pragma unroll
            for (int n = 0; n < 16; ++n)
                #pragma unroll
                for (int j = 0; j < 4; ++j) acc[n][j] = 0.f;
        }

        // ---- compute this k-step ----
        const uint32_t bufoff = buf ? BUFB : 0u;
        uint32_t a0[4];
        LDSM_X4(a0[0], a0[1], a0[2], a0[3], sAu + bufoff + aoff);
        const uint32_t bb = sBu + bufoff + boff;
        #pragma unroll
        for (int p = 0; p < 8; ++p) {
            uint32_t b[4];
            LDSM_X4(b[0], b[1], b[2], b[3], bb + p * (16 * PITCH));
            MMA16816(acc[2 * p],     a0[0], a0[1], a0[2], a0[3], b[0], b[1]);
            MMA16816(acc[2 * p + 1], a0[0], a0[1], a0[2], a0[3], b[2], b[3]);
        }
        __syncthreads();

        // ---- epilogue at the end of each 128-code chunk ----
        if ((g & 15) == 15) {
            const int codebase = (g >> 4) << 7;
            #pragma unroll
            for (int s = 0; s < 2; ++s) {
                float lbv = bv[s], lb2 = b2[s];
                int   lbi = bi[s];
                #pragma unroll
                for (int n = 0; n < 16; ++n) {
                    int c0 = codebase + n * 8 + ((lane & 3) << 1);
                    float s0 = fmaf(-2.f, acc[n][s * 2],     se2[c0]);
                    float s1 = fmaf(-2.f, acc[n][s * 2 + 1], se2[c0 + 1]);
                    if (s0 < lbv) { lb2 = lbv; lbv = s0; lbi = c0; }
                    else if (s0 < lb2) lb2 = s0;
                    if (s1 < lbv) { lb2 = lbv; lbv = s1; lbi = c0 + 1; }
                    else if (s1 < lb2) lb2 = s1;
                }
                bv[s] = lbv; b2[s] = lb2; bi[s] = lbi;
            }
        }
    }

    // ---- merge across the 4 lanes sharing each pixel row ----
    #pragma unroll
    for (int o = 1; o <= 2; o <<= 1) {
        #pragma unroll
        for (int s = 0; s < 2; ++s) {
            float ov = __shfl_xor_sync(0xFFFFFFFFu, bv[s], o);
            float o2 = __shfl_xor_sync(0xFFFFFFFFu, b2[s], o);
            int   oi = __shfl_xor_sync(0xFFFFFFFFu, bi[s], o);
            if (ov < bv[s] || (ov == bv[s] && oi < bi[s])) {
                b2[s] = fminf(bv[s], o2);
                bv[s] = ov; bi[s] = oi;
            } else {
                b2[s] = fminf(b2[s], ov);
            }
        }
    }
    if ((lane & 3) == 0) {
        #pragma unroll
        for (int s = 0; s < 2; ++s) {
            int prow = pix0 + wid * 16 + (lane >> 2) + s * 8;
            g_idx[prow] = bi[s];
            if (b2[s] - bv[s] < MARGIN) {
                int pos = atomicAdd(&g_nflag, 1);
                if (pos < FLAGCAP) g_flag[pos] = prow;
            }
        }
    }
}

// ============================================================
// K4: exact fp32 rescore of margin-flagged pixels (one warp each)
// ============================================================
__global__ __launch_bounds__(256) void k_fix(const float* __restrict__ z,
                                             const float* __restrict__ emb) {
    __shared__ float sx[8][256];
    const int w = threadIdx.x >> 5, lane = threadIdx.x & 31;
    int n = g_nflag; if (n > FLAGCAP) n = FLAGCAP;
    for (int f = blockIdx.x * 8 + w; f < n; f += gridDim.x * 8) {
        int pix = g_flag[f];
        const float* zb = z + (((size_t)(pix >> 12)) << 20) + (pix & 4095);
        for (int k = lane; k < EDIM; k += 32) sx[w][k] = zb[(size_t)k * HW];
        __syncwarp();
        float bv = 3.402823466e38f; int bi = 0;
        for (int c = lane; c < NEMB; c += 32) {
            const float* e = emb + (size_t)c * EDIM;
            float a0 = 0.f, a1 = 0.f, a2 = 0.f, a3 = 0.f;
            #pragma unroll 8
            for (int k = 0; k < EDIM; k += 4) {
                a0 = fmaf(sx[w][k],     e[k],     a0);
                a1 = fmaf(sx[w][k + 1], e[k + 1], a1);
                a2 = fmaf(sx[w][k + 2], e[k + 2], a2);
                a3 = fmaf(sx[w][k + 3], e[k + 3], a3);
            }
            float sc = g_e2[c] - 2.f * ((a0 + a1) + (a2 + a3));
            if (sc < bv) { bv = sc; bi = c; }
        }
        #pragma unroll
        for (int o = 16; o; o >>= 1) {
            float ov = __shfl_xor_sync(0xFFFFFFFFu, bv, o);
            int   oi = __shfl_xor_sync(0xFFFFFFFFu, bi, o);
            if (ov < bv || (ov == bv && oi < bi)) { bv = ov; bi = oi; }
        }
        if (lane == 0) g_idx[pix] = bi;
        __syncwarp();
    }
}

// ============================================================
// K5: gather z_q, write z_q_st = z_e + (z_q - z_e), loss partials
// ============================================================
__global__ __launch_bounds__(256)
void k_gather(const float* __restrict__ z, const float* __restrict__ emb,
              float* __restrict__ out) {
    __shared__ float sE[32 * 260];
    __shared__ float swarp[8];
    const int t = threadIdx.x;
    const int pix0 = blockIdx.x << 5;

    #pragma unroll
    for (int it = 0; it < 8; ++it) {
        int slot = t + (it << 8);
        int p = slot >> 6, c4 = slot & 63;
        int idx = g_idx[pix0 + p];
        float4 v = *reinterpret_cast<const float4*>(emb + (size_t)idx * EDIM + (c4 << 2));
        *reinterpret_cast<float4*>(&sE[p * 260 + (c4 << 2)]) = v;
    }
    __syncthreads();

    const float* zb = z   + (((size_t)(pix0 >> 12)) << 20) + (pix0 & 4095);
    float*       ob = out + (((size_t)(pix0 >> 12)) << 20) + (pix0 & 4095);

    float lsum = 0.f;
    #pragma unroll
    for (int it = 0; it < 8; ++it) {
        int slot = t + (it << 8);
        int hw = slot & 31, c4 = slot >> 5;
        float4 e = *reinterpret_cast<const float4*>(&sE[hw * 260 + (c4 << 2)]);
        float ev[4] = {e.x, e.y, e.z, e.w};
        #pragma unroll
        for (int j = 0; j < 4; ++j) {
            size_t gg = (size_t)((c4 << 2) + j) * HW + hw;
            float ze = zb[gg];
            float d = ev[j] - ze;
            ob[gg] = ze + d;
            lsum += d * d;
        }
    }
    #pragma unroll
    for (int o = 16; o; o >>= 1) lsum += __shfl_xor_sync(0xFFFFFFFFu, lsum, o);
    if ((t & 31) == 0) swarp[t >> 5] = lsum;
    __syncthreads();
    if (t == 0) {
        double s = 0.0;
        #pragma unroll
        for (int w = 0; w < 8; ++w) s += (double)swarp[w];
        g_part[blockIdx.x] = s;
    }
}

// ============================================================
// K6: loss finalize
// ============================================================
__global__ void k_loss(float* __restrict__ out, int out_size) {
    __shared__ double sd[256];
    int t = threadIdx.x;
    double s = 0.0;
    for (int i = t; i < 2048; i += 256) s += g_part[i];
    sd[t] = s;
    __syncthreads();
    for (int o = 128; o; o >>= 1) {
        if (t < o) sd[t] += sd[t + o];
        __syncthreads();
    }
    if (t == 0 && out_size > NC)
        out[NC] = (float)(0.25 * sd[0] / (double)NC);
}

// ============================================================
extern "C" void kernel_launch(void* const* d_in, const int* in_sizes, int n_in,
                              void* d_out, int out_size) {
    const float* z   = (const float*)d_in[0];
    const float* emb = (const float*)d_in[1];
    float* out = (float*)d_out;

    k_split <<<2048, 256>>>(z);
    k_prep_e<<<128,  256>>>(emb);
    k_mma   <<<512,  256>>>();
    k_fix   <<<256,  256>>>(z, emb);
    k_gather<<<2048, 256>>>(z, emb, out);
    k_loss  <<<1,    256>>>(out, out_size);
}

// round 9
// speedup vs baseline: 7.1918x; 4.5317x over previous
#include <cuda_runtime.h>
#include <cstdint>
#include <cstddef>

// VectorQuantizer on GB300 (sm_103a) — exact fp32 FFMA2 scoring (f32x2),
// 3-stage cp.async pipeline (canonical wait->sync->issue order), 1 barrier/step.
// z_e: (16,256,64,64) fp32 ; embedding: (1024,256) fp32

#define NEMB 1024
#define EDIM 256
#define HW   4096
#define NPIX 65536
#define NC   16777216

#define STG    32768          // per-stage: A 16KB + B 16KB
#define SM_E2  (3 * STG)      // 98304
#define SM_TOT (3 * STG + 4096)

// ---- device scratch ----
__device__ __align__(128) float g_Bt[EDIM * NEMB];   // [k][code] fp32 (emb transposed)
__device__ __align__(16) float  g_e2[NEMB];
__device__ int    g_idx[NPIX];
__device__ double g_part[2048];

// ---- packed f32x2 helpers ----
#define FMA2(d, a, b) asm("fma.rn.f32x2 %0, %1, %2, %0;" : "+l"(d) : "l"(a), "l"(b))

static __device__ __forceinline__ unsigned long long pack2(float x) {
    unsigned long long r;
    unsigned int u = __float_as_uint(x);
    asm("mov.b64 %0, {%1, %1};" : "=l"(r) : "r"(u));
    return r;
}
static __device__ __forceinline__ void unpack2(unsigned long long v, float& lo, float& hi) {
    unsigned int a, b;
    asm("mov.b64 {%0, %1}, %2;" : "=r"(a), "=r"(b) : "l"(v));
    lo = __uint_as_float(a);
    hi = __uint_as_float(b);
}
static __device__ __forceinline__ uint32_t s2u(const void* p) {
    uint32_t a;
    asm("{ .reg .u64 t; cvta.to.shared.u64 t, %1; cvt.u32.u64 %0, t; }" : "=r"(a) : "l"(p));
    return a;
}
static __device__ __forceinline__ void cpa16(uint32_t dst, const void* src) {
    asm volatile("cp.async.cg.shared.global [%0], [%1], 16;" :: "r"(dst), "l"(src));
}

// ============================================================
// K1: per-code squared norms. One warp per code.
// ============================================================
__global__ void k_e2(const float* __restrict__ emb) {
    int warp = (blockIdx.x * blockDim.x + threadIdx.x) >> 5;
    int lane = threadIdx.x & 31;
    if (warp >= NEMB) return;
    const float4* row = reinterpret_cast<const float4*>(emb + (size_t)warp * EDIM);
    float s = 0.f;
    #pragma unroll
    for (int i = lane; i < EDIM / 4; i += 32) {
        float4 v = row[i];
        s += v.x * v.x + v.y * v.y + v.z * v.z + v.w * v.w;
    }
    #pragma unroll
    for (int o = 16; o; o >>= 1) s += __shfl_xor_sync(0xFFFFFFFFu, s, o);
    if (lane == 0) g_e2[warp] = s;
}

// ============================================================
// K2: transpose embedding -> g_Bt[k][code]
// ============================================================
__global__ __launch_bounds__(256) void k_bt(const float* __restrict__ emb) {
    __shared__ float tile[32][33];
    const int tx = threadIdx.x & 31;
    const int ty = threadIdx.x >> 5;          // 0..7
    const int c0 = blockIdx.x << 5;           // code tile
    const int k0 = blockIdx.y << 5;           // k tile
    #pragma unroll
    for (int i = 0; i < 4; ++i)
        tile[ty + i * 8][tx] = emb[(size_t)(c0 + ty + i * 8) * EDIM + k0 + tx];
    __syncthreads();
    #pragma unroll
    for (int i = 0; i < 4; ++i)
        g_Bt[(size_t)(k0 + ty + i * 8) * NEMB + c0 + tx] = tile[tx][ty + i * 8];
}

// ============================================================
// K3: fused GEMM + argmin, exact fp32 via f32x2.
// CTA = 128 pixels x 1024 codes (8 chunks of 128).
// 64 global steps = 8 cc x 8 ksteps of 32 k. 3-stage cp.async,
// order per step: wait(own) -> __syncthreads -> issue g+2 -> compute.
// Thread tile 8 pix x 8 codes.
// ============================================================
__global__ __launch_bounds__(256, 2) void k_argmin(const float* __restrict__ z) {
    extern __shared__ char smem[];
    const uint32_t sbase = s2u(smem);
    float* se2 = reinterpret_cast<float*>(smem + SM_E2);

    const int t  = threadIdx.x;
    const int tx = t & 15;             // 8 codes (tx*8..+7)
    const int ty = t >> 4;             // 8 pixels (ty*8..+7)
    const int pix0 = blockIdx.x << 7;
    const float* zb = z + (((size_t)(pix0 >> 12)) << 20) + (pix0 & 4095);

    #pragma unroll
    for (int i = 0; i < 4; ++i) se2[t + (i << 8)] = g_e2[t + (i << 8)];

    // loader granule coords (4 granules each for A and B per step)
    const int lr0 = t >> 5;            // rows lr0, lr0+8, lr0+16, lr0+24
    const int lc  = (t & 31) << 2;     // float column (16B granule)

    float bestv[8];
    int   besti[8];
    #pragma unroll
    for (int i = 0; i < 8; ++i) { bestv[i] = 3.402823466e38f; besti[i] = 0; }

    unsigned long long acc[8][4];
    #pragma unroll
    for (int i = 0; i < 8; ++i)
        #pragma unroll
        for (int j = 0; j < 4; ++j) acc[i][j] = 0ULL;

    // ---- prologue: issue steps 0 and 1 ----
    #pragma unroll
    for (int p = 0; p < 2; ++p) {
        const int kc = p & 7, cc = p >> 3;
        const uint32_t ba = sbase + p * STG;
        #pragma unroll
        for (int i = 0; i < 4; ++i) {
            int r = lr0 + (i << 3);
            cpa16(ba + r * 512 + (lc << 2), &zb[(size_t)(kc * 32 + r) * HW + lc]);
            cpa16(ba + 16384 + r * 512 + (lc << 2),
                  &g_Bt[(size_t)(kc * 32 + r) * NEMB + cc * 128 + lc]);
        }
        asm volatile("cp.async.commit_group;" ::: "memory");
    }

    #pragma unroll 1
    for (int g = 0; g < 64; ++g) {
        // 1. own group g complete (g, g+1 in flight; g+2 not yet issued)
        if (g < 63) {
            asm volatile("cp.async.wait_group 1;" ::: "memory");
        } else {
            asm volatile("cp.async.wait_group 0;" ::: "memory");
        }
        // 2. CTA-wide: group-g data visible, buf (g-1)%3 reads all done
        __syncthreads();

        // 3. issue group g+2 into buffer (g+2)%3 == (g-1)%3
        if (g + 2 < 64) {
            const int g2 = g + 2;
            const int kc = g2 & 7, cc = g2 >> 3;
            const uint32_t ba = sbase + (g2 % 3) * STG;
            #pragma unroll
            for (int i = 0; i < 4; ++i) {
                int r = lr0 + (i << 3);
                cpa16(ba + r * 512 + (lc << 2), &zb[(size_t)(kc * 32 + r) * HW + lc]);
                cpa16(ba + 16384 + r * 512 + (lc << 2),
                      &g_Bt[(size_t)(kc * 32 + r) * NEMB + cc * 128 + lc]);
            }
            asm volatile("cp.async.commit_group;" ::: "memory");
        }

        // 4. compute on buffer g%3
        const char* pA = smem + (g % 3) * STG;
        const char* pB = pA + 16384;

        #pragma unroll 8
        for (int kk = 0; kk < 32; ++kk) {
            float4 a0 = *reinterpret_cast<const float4*>(pA + kk * 512 + (ty << 5));
            float4 a1 = *reinterpret_cast<const float4*>(pA + kk * 512 + (ty << 5) + 16);
            ulonglong2 b01 = *reinterpret_cast<const ulonglong2*>(pB + kk * 512 + (tx << 5));
            ulonglong2 b23 = *reinterpret_cast<const ulonglong2*>(pB + kk * 512 + (tx << 5) + 16);
            unsigned long long bvx[4] = {b01.x, b01.y, b23.x, b23.y};
            unsigned long long aa[8];
            aa[0] = pack2(a0.x); aa[1] = pack2(a0.y);
            aa[2] = pack2(a0.z); aa[3] = pack2(a0.w);
            aa[4] = pack2(a1.x); aa[5] = pack2(a1.y);
            aa[6] = pack2(a1.z); aa[7] = pack2(a1.w);
            #pragma unroll
            for (int i = 0; i < 8; ++i)
                #pragma unroll
                for (int j = 0; j < 4; ++j)
                    FMA2(acc[i][j], aa[i], bvx[j]);
        }

        // ---- epilogue after the 8th kstep of each code-chunk ----
        if ((g & 7) == 7) {
            const int code0 = (g >> 3) << 7;
            float4 e2a = *reinterpret_cast<const float4*>(&se2[code0 + (tx << 3)]);
            float4 e2b = *reinterpret_cast<const float4*>(&se2[code0 + (tx << 3) + 4]);
            float e2v[8] = {e2a.x, e2a.y, e2a.z, e2a.w, e2b.x, e2b.y, e2b.z, e2b.w};
            #pragma unroll
            for (int i = 0; i < 8; ++i) {
                #pragma unroll
                for (int j = 0; j < 4; ++j) {
                    float lo, hi;
                    unpack2(acc[i][j], lo, hi);
                    acc[i][j] = 0ULL;
                    float s0 = fmaf(-2.f, lo, e2v[2 * j]);
                    float s1 = fmaf(-2.f, hi, e2v[2 * j + 1]);
                    int c = code0 + (tx << 3) + 2 * j;
                    if (s0 < bestv[i]) { bestv[i] = s0; besti[i] = c; }
                    if (s1 < bestv[i]) { bestv[i] = s1; besti[i] = c + 1; }
                }
            }
        }
    }

    // ---- cross-thread argmin over tx (16-lane halves), lowest index on ties ----
    #pragma unroll
    for (int o = 8; o; o >>= 1) {
        #pragma unroll
        for (int i = 0; i < 8; ++i) {
            float ov = __shfl_xor_sync(0xFFFFFFFFu, bestv[i], o);
            int   oi = __shfl_xor_sync(0xFFFFFFFFu, besti[i], o);
            if (ov < bestv[i] || (ov == bestv[i] && oi < besti[i])) {
                bestv[i] = ov; besti[i] = oi;
            }
        }
    }
    if (tx == 0) {
        #pragma unroll
        for (int i = 0; i < 8; ++i) g_idx[pix0 + (ty << 3) + i] = besti[i];
    }
}

// ============================================================
// K4: gather z_q, write z_q_st = z_e + (z_q - z_e), loss partials
// ============================================================
__global__ __launch_bounds__(256)
void k_gather(const float* __restrict__ z, const float* __restrict__ emb,
              float* __restrict__ out) {
    __shared__ float sE[32 * 260];
    __shared__ float swarp[8];
    const int t = threadIdx.x;
    const int pix0 = blockIdx.x << 5;

    #pragma unroll
    for (int it = 0; it < 8; ++it) {
        int slot = t + (it << 8);
        int p = slot >> 6, c4 = slot & 63;
        int idx = g_idx[pix0 + p];
        float4 v = *reinterpret_cast<const float4*>(emb + (size_t)idx * EDIM + (c4 << 2));
        *reinterpret_cast<float4*>(&sE[p * 260 + (c4 << 2)]) = v;
    }
    __syncthreads();

    const float* zb = z   + (((size_t)(pix0 >> 12)) << 20) + (pix0 & 4095);
    float*       ob = out + (((size_t)(pix0 >> 12)) << 20) + (pix0 & 4095);

    float lsum = 0.f;
    #pragma unroll
    for (int it = 0; it < 8; ++it) {
        int slot = t + (it << 8);
        int hw = slot & 31, c4 = slot >> 5;
        float4 e = *reinterpret_cast<const float4*>(&sE[hw * 260 + (c4 << 2)]);
        float ev[4] = {e.x, e.y, e.z, e.w};
        #pragma unroll
        for (int j = 0; j < 4; ++j) {
            size_t gg = (size_t)((c4 << 2) + j) * HW + hw;
            float ze = zb[gg];
            float d = ev[j] - ze;
            ob[gg] = ze + d;
            lsum += d * d;
        }
    }
    #pragma unroll
    for (int o = 16; o; o >>= 1) lsum += __shfl_xor_sync(0xFFFFFFFFu, lsum, o);
    if ((t & 31) == 0) swarp[t >> 5] = lsum;
    __syncthreads();
    if (t == 0) {
        double s = 0.0;
        #pragma unroll
        for (int w = 0; w < 8; ++w) s += (double)swarp[w];
        g_part[blockIdx.x] = s;
    }
}

// ============================================================
// K5: loss finalize
// ============================================================
__global__ void k_loss(float* __restrict__ out, int out_size) {
    __shared__ double sd[256];
    int t = threadIdx.x;
    double s = 0.0;
    for (int i = t; i < 2048; i += 256) s += g_part[i];
    sd[t] = s;
    __syncthreads();
    for (int o = 128; o; o >>= 1) {
        if (t < o) sd[t] += sd[t + o];
        __syncthreads();
    }
    if (t == 0 && out_size > NC)
        out[NC] = (float)(0.25 * sd[0] / (double)NC);
}

// ============================================================
extern "C" void kernel_launch(void* const* d_in, const int* in_sizes, int n_in,
                              void* d_out, int out_size) {
    const float* z   = (const float*)d_in[0];
    const float* emb = (const float*)d_in[1];
    float* out = (float*)d_out;

    cudaFuncSetAttribute(k_argmin, cudaFuncAttributeMaxDynamicSharedMemorySize, SM_TOT);

    k_e2    <<<128, 256>>>(emb);
    {
        dim3 grid(32, 8);
        k_bt<<<grid, 256>>>(emb);
    }
    k_argmin<<<512, 256, SM_TOT>>>(z);
    k_gather<<<2048, 256>>>(z, emb, out);
    k_loss  <<<1, 256>>>(out, out_size);
}